// round 3
// baseline (speedup 1.0000x reference)
#include <cuda_runtime.h>
#include <math.h>

// ---------------- problem constants (fixed by the dataset) ----------------
#define NN     200000      // nodes
#define NEDGE  800000      // edges
#define CBB    480         // backbone channels
#define CT     484         // backbone + seg channels (gatherable)
#define FDIM   128         // feature map H = W
#define NPIX   (FDIM*FDIM) // 16384
#define HID    128         // hidden dim
#define KIN    488         // MLP1 input dim
#define KPAD   512         // padded K (16 chunks of 32)
#define LDA    132         // smem row stride (16B aligned, conflict-friendly)

// smem layout (floats): [h1/A region 128*132][B region 32*132][params 12*128]
#define BS_OFF  (128*LDA)
#define P_OFF   (BS_OFF + 32*LDA)
#define SMEM_FLOATS (P_OFF + 12*128)

// ---------------- device scratch (static; no allocations) ----------------
__device__ float g_ft[(size_t)NPIX * CT];   // transposed/interleaved feature map (~31.7MB)
__device__ int   g_deg[NN];
__device__ int   g_maxdeg;
__device__ int   g_e64;                     // 1 if edge_index is int64, 0 if int32

// ---------------- packed f32x2 helpers ----------------
__device__ __forceinline__ void fma2(unsigned long long& d, unsigned long long a, unsigned long long b) {
    asm("fma.rn.f32x2 %0, %1, %2, %0;" : "+l"(d) : "l"(a), "l"(b));
}
__device__ __forceinline__ unsigned long long bcast2(float a) {
    unsigned long long r;
    asm("mov.b64 %0, {%1, %1};" : "=l"(r) : "r"(__float_as_uint(a)));
    return r;
}
__device__ __forceinline__ float lo32(unsigned long long v) { return __uint_as_float((unsigned)v); }
__device__ __forceinline__ float hi32(unsigned long long v) { return __uint_as_float((unsigned)(v >> 32)); }

// ---------------- K0: detect edge dtype (int64 -> odd int32 words are 0) ----------------
__global__ void k_detect(const int* __restrict__ e) {
    int t = threadIdx.x;                   // 32 threads
    int nz = (e[2 * t + 1] != 0) ? 1 : 0;  // high word if int64, real value if int32
    unsigned m = __ballot_sync(0xffffffffu, nz);
    if (t == 0) g_e64 = (m == 0u) ? 1 : 0;
}

// ---------------- K1: zero degree array + maxdeg ----------------
__global__ void k_zero() {
    int i = blockIdx.x * blockDim.x + threadIdx.x;
    if (i < NN) g_deg[i] = 0;
    if (i == 0) g_maxdeg = 0;
}

// ---------------- K2: degree histogram ----------------
__global__ void k_degree(const void* __restrict__ eptr) {
    const int total = 2 * NEDGE;
    const bool is64 = (g_e64 != 0);
    const long long* __restrict__ e64 = (const long long*)eptr;
    const int* __restrict__ e32 = (const int*)eptr;
    for (int i = blockIdx.x * blockDim.x + threadIdx.x; i < total; i += gridDim.x * blockDim.x) {
        int idx = is64 ? (int)e64[i] : e32[i];
        atomicAdd(&g_deg[idx], 1);
    }
}

// ---------------- K3: max degree ----------------
__global__ void k_max() {
    int i = blockIdx.x * blockDim.x + threadIdx.x;
    int v = (i < NN) ? g_deg[i] : 0;
    #pragma unroll
    for (int o = 16; o > 0; o >>= 1) v = max(v, __shfl_down_sync(0xffffffffu, v, o));
    if ((threadIdx.x & 31) == 0) atomicMax(&g_maxdeg, v);
}

// ---------------- K4: transpose (C,H,W) -> (pix, 484) interleaving backbone+seg ----------------
__global__ void k_transpose(const float* __restrict__ bb, const float* __restrict__ seg) {
    __shared__ float t[32][33];
    const int tx = threadIdx.x, ty = threadIdx.y;  // 32 x 8
    const int c0 = blockIdx.x * 32;
    const int p0 = blockIdx.y * 32;
    #pragma unroll
    for (int i = 0; i < 4; i++) {
        int c = c0 + ty + i * 8;
        float v = 0.0f;
        if (c < CT) {
            v = (c < CBB) ? bb[(size_t)c * NPIX + p0 + tx]
                          : seg[(size_t)(c - CBB) * NPIX + p0 + tx];
        }
        t[ty + i * 8][tx] = v;
    }
    __syncthreads();
    #pragma unroll
    for (int i = 0; i < 4; i++) {
        int p = p0 + ty + i * 8;
        int c = c0 + tx;
        if (c < CT) g_ft[(size_t)p * CT + c] = t[tx][ty + i * 8];
    }
}

// ---------------- K5: fused gather + MLP (GEMM1 + GEMM2) ----------------
__global__ void __launch_bounds__(256, 2) k_main(
    const float* __restrict__ verts,
    const float* __restrict__ W1,
    const float* __restrict__ b1,
    const float* __restrict__ W2,
    const float* __restrict__ b2,
    float* __restrict__ out)
{
    extern __shared__ float sm[];
    float* h1s = sm;            // 128 x 132 : A chunks (rows 0..31) in phase1, full h1^T in phase2
    float* Bs  = sm + BS_OFF;   // 32 x 132  : W1/W2 chunk
    float* Pf  = sm + P_OFF;    // node params
    int*   Pi  = (int*)Pf;

    const int tid = threadIdx.x;
    const int m0 = blockIdx.x * 128;

    // -------- per-node param precompute --------
    if (tid < 128) {
        int node = min(m0 + tid, NN - 1);
        float vx = verts[2 * node + 0];
        float vy = verts[2 * node + 1];
        float ix = vx * (127.0f / 512.0f);
        float iy = vy * (127.0f / 512.0f);
        float fx = floorf(ix), fy = floorf(iy);
        float wx = ix - fx, wy = iy - fy;
        int x0 = min(max((int)fx, 0), FDIM - 1);
        int x1 = min(x0 + 1, FDIM - 1);
        int y0 = min(max((int)fy, 0), FDIM - 1);
        int y1 = min(y0 + 1, FDIM - 1);
        Pi[0 * 128 + tid] = (y0 * FDIM + x0) * CT;
        Pi[1 * 128 + tid] = (y0 * FDIM + x1) * CT;
        Pi[2 * 128 + tid] = (y1 * FDIM + x0) * CT;
        Pi[3 * 128 + tid] = (y1 * FDIM + x1) * CT;
        Pf[4 * 128 + tid] = (1.0f - wx) * (1.0f - wy);
        Pf[5 * 128 + tid] = wx * (1.0f - wy);
        Pf[6 * 128 + tid] = (1.0f - wx) * wy;
        Pf[7 * 128 + tid] = wx * wy;
        Pf[8 * 128 + tid] = vx * (1.0f / 512.0f);
        Pf[9 * 128 + tid] = vy * (1.0f / 512.0f);
        Pf[10 * 128 + tid] = (float)g_deg[node] / ((float)g_maxdeg + 1e-6f);
        float dx = fminf(vx, 512.0f - vx);
        float dy = fminf(vy, 512.0f - vy);
        Pf[11 * 128 + tid] = fminf(dx, dy) * (1.0f / 256.0f);
    }
    __syncthreads();

    const int warp = tid >> 5, lane = tid & 31;
    const int wm = warp & 3, wn = warp >> 2;            // 4 x 2 warps
    const int mb = wm * 32 + (lane >> 3) * 8;           // 8 contiguous m
    const int nb = wn * 64 + (lane & 7) * 8;            // 8 contiguous n

    unsigned long long acc[8][4];
    #pragma unroll
    for (int i = 0; i < 8; i++)
        #pragma unroll
        for (int j = 0; j < 4; j++) acc[i][j] = 0ull;

    const float* __restrict__ ft = g_ft;

    // ================= GEMM1: K' = 512 in 16 chunks of 32 =================
    // internal k' order: [0..483]=channels (backbone+seg), 484/485=coords, 486=deg, 487=dist, >=488 zero
    for (int kc = 0; kc < 16; kc++) {
        const int k0 = kc * 32;
        // ---- build A chunk: h1s[lane(=k)][m], warp = m lane-group ----
        {
            int kp = k0 + lane;
            if (kp < CT) {
                #pragma unroll 4
                for (int it = 0; it < 16; it++) {
                    int m = it * 8 + warp;
                    int q00 = Pi[m], q01 = Pi[128 + m], q10 = Pi[256 + m], q11 = Pi[384 + m];
                    float w00 = Pf[4 * 128 + m], w01 = Pf[5 * 128 + m];
                    float w10 = Pf[6 * 128 + m], w11 = Pf[7 * 128 + m];
                    float v = w00 * ft[q00 + kp] + w01 * ft[q01 + kp]
                            + w10 * ft[q10 + kp] + w11 * ft[q11 + kp];
                    h1s[lane * LDA + m] = v;
                }
            } else {
                #pragma unroll 4
                for (int it = 0; it < 16; it++) {
                    int m = it * 8 + warp;
                    float v = (kp < KIN) ? Pf[(8 + (kp - CT)) * 128 + m] : 0.0f;
                    h1s[lane * LDA + m] = v;
                }
            }
        }
        // ---- load B chunk: Bs[k][n] = W1[n][permuted col] ----
        {
            int kp = k0 + lane;
            int col;
            if      (kp < CT)   col = kp + 2;   // channel c -> W1 col c+2 (backbone+seg)
            else if (kp == 484) col = 0;        // coord x
            else if (kp == 485) col = 1;        // coord y
            else if (kp == 486) col = 486;      // degree_norm
            else if (kp == 487) col = 487;      // dist_to_boundary
            else                col = -1;       // zero pad
            #pragma unroll 4
            for (int it = 0; it < 16; it++) {
                int n = it * 8 + warp;
                Bs[lane * LDA + n] = (col >= 0) ? W1[n * KIN + col] : 0.0f;
            }
        }
        __syncthreads();
        // ---- math ----
        #pragma unroll 4
        for (int kk = 0; kk < 32; kk++) {
            const float* ar = h1s + kk * LDA + mb;
            float4 a0 = *(const float4*)ar;
            float4 a1 = *(const float4*)(ar + 4);
            const float* br = Bs + kk * LDA + nb;
            ulonglong2 bq0 = *(const ulonglong2*)br;
            ulonglong2 bq1 = *(const ulonglong2*)(br + 4);
            unsigned long long av[8];
            av[0] = bcast2(a0.x); av[1] = bcast2(a0.y); av[2] = bcast2(a0.z); av[3] = bcast2(a0.w);
            av[4] = bcast2(a1.x); av[5] = bcast2(a1.y); av[6] = bcast2(a1.z); av[7] = bcast2(a1.w);
            unsigned long long bv[4] = {bq0.x, bq0.y, bq1.x, bq1.y};
            #pragma unroll
            for (int mi = 0; mi < 8; mi++)
                #pragma unroll
                for (int pj = 0; pj < 4; pj++)
                    fma2(acc[mi][pj], av[mi], bv[pj]);
        }
        __syncthreads();
    }

    // ---- epilogue 1: relu(acc + b1) -> h1s transposed [k=n][m] ----
    {
        float4 bl = *(const float4*)(b1 + nb);
        float4 bh = *(const float4*)(b1 + nb + 4);
        float bb1[8] = {bl.x, bl.y, bl.z, bl.w, bh.x, bh.y, bh.z, bh.w};
        #pragma unroll
        for (int nj = 0; nj < 8; nj++) {
            float4 v0, v1;
            float* p0 = (float*)&v0; float* p1 = (float*)&v1;
            #pragma unroll
            for (int mi = 0; mi < 8; mi++) {
                unsigned long long a = acc[mi][nj >> 1];
                float t = (nj & 1) ? hi32(a) : lo32(a);
                t = fmaxf(t + bb1[nj], 0.0f);
                if (mi < 4) p0[mi] = t; else p1[mi - 4] = t;
            }
            *(float4*)(h1s + (nb + nj) * LDA + mb)     = v0;
            *(float4*)(h1s + (nb + nj) * LDA + mb + 4) = v1;
        }
    }

    #pragma unroll
    for (int i = 0; i < 8; i++)
        #pragma unroll
        for (int j = 0; j < 4; j++) acc[i][j] = 0ull;

    // ================= GEMM2: K = 128 in 4 chunks of 32 =================
    for (int kc = 0; kc < 4; kc++) {
        const int k0 = kc * 32;
        #pragma unroll 4
        for (int it = 0; it < 16; it++) {
            int n = it * 8 + warp;
            Bs[lane * LDA + n] = W2[n * HID + k0 + lane];
        }
        __syncthreads();   // orders h1s epilogue writes (first iter) + Bs loads before math
        #pragma unroll 4
        for (int kk = 0; kk < 32; kk++) {
            const float* ar = h1s + (k0 + kk) * LDA + mb;
            float4 a0 = *(const float4*)ar;
            float4 a1 = *(const float4*)(ar + 4);
            const float* br = Bs + kk * LDA + nb;
            ulonglong2 bq0 = *(const ulonglong2*)br;
            ulonglong2 bq1 = *(const ulonglong2*)(br + 4);
            unsigned long long av[8];
            av[0] = bcast2(a0.x); av[1] = bcast2(a0.y); av[2] = bcast2(a0.z); av[3] = bcast2(a0.w);
            av[4] = bcast2(a1.x); av[5] = bcast2(a1.y); av[6] = bcast2(a1.z); av[7] = bcast2(a1.w);
            unsigned long long bv[4] = {bq0.x, bq0.y, bq1.x, bq1.y};
            #pragma unroll
            for (int mi = 0; mi < 8; mi++)
                #pragma unroll
                for (int pj = 0; pj < 4; pj++)
                    fma2(acc[mi][pj], av[mi], bv[pj]);
        }
        __syncthreads();
    }

    // ---- epilogue 2: relu(acc + b2) -> out ----
    {
        float4 bl = *(const float4*)(b2 + nb);
        float4 bh = *(const float4*)(b2 + nb + 4);
        float bb2[8] = {bl.x, bl.y, bl.z, bl.w, bh.x, bh.y, bh.z, bh.w};
        #pragma unroll
        for (int mi = 0; mi < 8; mi++) {
            int m = m0 + mb + mi;
            if (m < NN) {
                float4 v0, v1;
                float* p0 = (float*)&v0; float* p1 = (float*)&v1;
                #pragma unroll
                for (int nj = 0; nj < 8; nj++) {
                    unsigned long long a = acc[mi][nj >> 1];
                    float t = (nj & 1) ? hi32(a) : lo32(a);
                    t = fmaxf(t + bb2[nj], 0.0f);
                    if (nj < 4) p0[nj] = t; else p1[nj - 4] = t;
                }
                *(float4*)(out + (size_t)m * HID + nb)     = v0;
                *(float4*)(out + (size_t)m * HID + nb + 4) = v1;
            }
        }
    }
}

// ---------------- launch ----------------
extern "C" void kernel_launch(void* const* d_in, const int* in_sizes, int n_in,
                              void* d_out, int out_size)
{
    const float* verts = (const float*)d_in[0];
    const float* bb    = (const float*)d_in[1];
    const float* seg   = (const float*)d_in[2];
    const void*  edges = d_in[3];
    const float* W1    = (const float*)d_in[4];
    const float* b1    = (const float*)d_in[5];
    const float* W2    = (const float*)d_in[6];
    const float* b2    = (const float*)d_in[7];
    float* out = (float*)d_out;

    k_detect<<<1, 32>>>((const int*)edges);
    k_zero<<<(NN + 255) / 256, 256>>>();
    k_transpose<<<dim3(16, NPIX / 32), dim3(32, 8)>>>(bb, seg);
    k_degree<<<2048, 256>>>(edges);
    k_max<<<(NN + 255) / 256, 256>>>();

    size_t smem = (size_t)SMEM_FLOATS * sizeof(float);   // 90624 B
    cudaFuncSetAttribute(k_main, cudaFuncAttributeMaxDynamicSharedMemorySize, (int)smem);
    k_main<<<(NN + 127) / 128, 256, smem>>>(verts, W1, b1, W2, b2, out);
}

// round 4
// speedup vs baseline: 1.5687x; 1.5687x over previous
#include <cuda_runtime.h>
#include <math.h>

// ---------------- problem constants (fixed by the dataset) ----------------
#define NN     200000      // nodes
#define NEDGE  800000      // edges
#define CBB    480         // backbone channels
#define CT     484         // backbone + seg channels (gatherable)
#define FDIM   128         // feature map H = W
#define NPIX   (FDIM*FDIM) // 16384
#define HID    128         // hidden dim
#define KIN    488         // MLP1 input dim
#define KPAD   512         // padded K (16 chunks of 32)
#define LDA    132         // smem row stride (16B aligned, conflict-friendly)

// smem layout (floats): [h1/A region 128*132][B region 32*132][params 12*128]
#define BS_OFF  (128*LDA)
#define P_OFF   (BS_OFF + 32*LDA)
#define SMEM_FLOATS (P_OFF + 12*128)

// ---------------- device scratch (static; no allocations) ----------------
__device__ float g_ft[(size_t)NPIX * CT];   // transposed/interleaved feature map (~31.7MB)
__device__ int   g_deg[NN];
__device__ int   g_maxdeg;
__device__ int   g_e64;                     // 1 if edge_index is int64, 0 if int32

// ---------------- packed f32x2 helpers ----------------
__device__ __forceinline__ void fma2(unsigned long long& d, unsigned long long a, unsigned long long b) {
    asm("fma.rn.f32x2 %0, %1, %2, %0;" : "+l"(d) : "l"(a), "l"(b));
}
__device__ __forceinline__ unsigned long long bcast2(float a) {
    unsigned long long r;
    asm("mov.b64 %0, {%1, %1};" : "=l"(r) : "r"(__float_as_uint(a)));
    return r;
}
__device__ __forceinline__ float lo32(unsigned long long v) { return __uint_as_float((unsigned)v); }
__device__ __forceinline__ float hi32(unsigned long long v) { return __uint_as_float((unsigned)(v >> 32)); }

// ---------------- K0: detect edge dtype (int64 -> odd int32 words are 0) ----------------
__global__ void k_detect(const int* __restrict__ e) {
    int t = threadIdx.x;                   // 32 threads
    int nz = (e[2 * t + 1] != 0) ? 1 : 0;  // high word if int64, real value if int32
    unsigned m = __ballot_sync(0xffffffffu, nz);
    if (t == 0) g_e64 = (m == 0u) ? 1 : 0;
}

// ---------------- K1: zero degree array + maxdeg ----------------
__global__ void k_zero() {
    int i = blockIdx.x * blockDim.x + threadIdx.x;
    if (i < NN) g_deg[i] = 0;
    if (i == 0) g_maxdeg = 0;
}

// ---------------- K2: degree histogram ----------------
__global__ void k_degree(const void* __restrict__ eptr) {
    const int total = 2 * NEDGE;
    const bool is64 = (g_e64 != 0);
    const long long* __restrict__ e64 = (const long long*)eptr;
    const int* __restrict__ e32 = (const int*)eptr;
    for (int i = blockIdx.x * blockDim.x + threadIdx.x; i < total; i += gridDim.x * blockDim.x) {
        int idx = is64 ? (int)e64[i] : e32[i];
        atomicAdd(&g_deg[idx], 1);
    }
}

// ---------------- K3: max degree ----------------
__global__ void k_max() {
    int i = blockIdx.x * blockDim.x + threadIdx.x;
    int v = (i < NN) ? g_deg[i] : 0;
    #pragma unroll
    for (int o = 16; o > 0; o >>= 1) v = max(v, __shfl_down_sync(0xffffffffu, v, o));
    if ((threadIdx.x & 31) == 0) atomicMax(&g_maxdeg, v);
}

// ---------------- K4: transpose (C,H,W) -> (pix, 484) interleaving backbone+seg ----------------
__global__ void k_transpose(const float* __restrict__ bb, const float* __restrict__ seg) {
    __shared__ float t[32][33];
    const int tx = threadIdx.x, ty = threadIdx.y;  // 32 x 8
    const int c0 = blockIdx.x * 32;
    const int p0 = blockIdx.y * 32;
    #pragma unroll
    for (int i = 0; i < 4; i++) {
        int c = c0 + ty + i * 8;
        float v = 0.0f;
        if (c < CT) {
            v = (c < CBB) ? bb[(size_t)c * NPIX + p0 + tx]
                          : seg[(size_t)(c - CBB) * NPIX + p0 + tx];
        }
        t[ty + i * 8][tx] = v;
    }
    __syncthreads();
    #pragma unroll
    for (int i = 0; i < 4; i++) {
        int p = p0 + ty + i * 8;
        int c = c0 + tx;
        if (c < CT) g_ft[(size_t)p * CT + c] = t[tx][ty + i * 8];
    }
}

// ---------------- K5: fused gather + MLP (GEMM1 + GEMM2) ----------------
__global__ void __launch_bounds__(256, 2) k_main(
    const float* __restrict__ verts,
    const float* __restrict__ W1,
    const float* __restrict__ b1,
    const float* __restrict__ W2,
    const float* __restrict__ b2,
    float* __restrict__ out)
{
    extern __shared__ float sm[];
    float* h1s = sm;            // 128 x 132 : A chunks (rows 0..31) in phase1, full h1^T in phase2
    float* Bs  = sm + BS_OFF;   // 32 x 132  : W1/W2 chunk
    float* Pf  = sm + P_OFF;    // node params
    int*   Pi  = (int*)Pf;

    const int tid = threadIdx.x;
    const int m0 = blockIdx.x * 128;

    // -------- per-node param precompute --------
    if (tid < 128) {
        int node = min(m0 + tid, NN - 1);
        float vx = verts[2 * node + 0];
        float vy = verts[2 * node + 1];
        float ix = vx * (127.0f / 512.0f);
        float iy = vy * (127.0f / 512.0f);
        float fx = floorf(ix), fy = floorf(iy);
        float wx = ix - fx, wy = iy - fy;
        int x0 = min(max((int)fx, 0), FDIM - 1);
        int x1 = min(x0 + 1, FDIM - 1);
        int y0 = min(max((int)fy, 0), FDIM - 1);
        int y1 = min(y0 + 1, FDIM - 1);
        Pi[0 * 128 + tid] = (y0 * FDIM + x0) * CT;
        Pi[1 * 128 + tid] = (y0 * FDIM + x1) * CT;
        Pi[2 * 128 + tid] = (y1 * FDIM + x0) * CT;
        Pi[3 * 128 + tid] = (y1 * FDIM + x1) * CT;
        Pf[4 * 128 + tid] = (1.0f - wx) * (1.0f - wy);
        Pf[5 * 128 + tid] = wx * (1.0f - wy);
        Pf[6 * 128 + tid] = (1.0f - wx) * wy;
        Pf[7 * 128 + tid] = wx * wy;
        Pf[8 * 128 + tid] = vx * (1.0f / 512.0f);
        Pf[9 * 128 + tid] = vy * (1.0f / 512.0f);
        Pf[10 * 128 + tid] = (float)g_deg[node] / ((float)g_maxdeg + 1e-6f);
        float dx = fminf(vx, 512.0f - vx);
        float dy = fminf(vy, 512.0f - vy);
        Pf[11 * 128 + tid] = fminf(dx, dy) * (1.0f / 256.0f);
    }
    __syncthreads();

    const int warp = tid >> 5, lane = tid & 31;
    const int wm = warp & 3, wn = warp >> 2;            // 4 x 2 warps
    const int mb = wm * 32 + (lane >> 3) * 8;           // 8 contiguous m
    const int nb = wn * 64 + (lane & 7) * 8;            // 8 contiguous n

    unsigned long long acc[8][4];
    #pragma unroll
    for (int i = 0; i < 8; i++)
        #pragma unroll
        for (int j = 0; j < 4; j++) acc[i][j] = 0ull;

    const float* __restrict__ ft = g_ft;

    // ================= GEMM1: K' = 512 in 16 chunks of 32 =================
    // internal k' order: [0..483]=channels (backbone+seg), 484/485=coords, 486=deg, 487=dist, >=488 zero
    for (int kc = 0; kc < 16; kc++) {
        const int k0 = kc * 32;
        // ---- build A chunk: h1s[lane(=k)][m], warp = m lane-group ----
        {
            int kp = k0 + lane;
            if (kp < CT) {
                #pragma unroll 4
                for (int it = 0; it < 16; it++) {
                    int m = it * 8 + warp;
                    int q00 = Pi[m], q01 = Pi[128 + m], q10 = Pi[256 + m], q11 = Pi[384 + m];
                    float w00 = Pf[4 * 128 + m], w01 = Pf[5 * 128 + m];
                    float w10 = Pf[6 * 128 + m], w11 = Pf[7 * 128 + m];
                    float v = w00 * ft[q00 + kp] + w01 * ft[q01 + kp]
                            + w10 * ft[q10 + kp] + w11 * ft[q11 + kp];
                    h1s[lane * LDA + m] = v;
                }
            } else {
                #pragma unroll 4
                for (int it = 0; it < 16; it++) {
                    int m = it * 8 + warp;
                    float v = (kp < KIN) ? Pf[(8 + (kp - CT)) * 128 + m] : 0.0f;
                    h1s[lane * LDA + m] = v;
                }
            }
        }
        // ---- load B chunk: Bs[k][n] = W1[n][permuted col] ----
        {
            int kp = k0 + lane;
            int col;
            if      (kp < CT)   col = kp + 2;   // channel c -> W1 col c+2 (backbone+seg)
            else if (kp == 484) col = 0;        // coord x
            else if (kp == 485) col = 1;        // coord y
            else if (kp == 486) col = 486;      // degree_norm
            else if (kp == 487) col = 487;      // dist_to_boundary
            else                col = -1;       // zero pad
            #pragma unroll 4
            for (int it = 0; it < 16; it++) {
                int n = it * 8 + warp;
                Bs[lane * LDA + n] = (col >= 0) ? W1[n * KIN + col] : 0.0f;
            }
        }
        __syncthreads();
        // ---- math ----
        #pragma unroll 4
        for (int kk = 0; kk < 32; kk++) {
            const float* ar = h1s + kk * LDA + mb;
            float4 a0 = *(const float4*)ar;
            float4 a1 = *(const float4*)(ar + 4);
            const float* br = Bs + kk * LDA + nb;
            ulonglong2 bq0 = *(const ulonglong2*)br;
            ulonglong2 bq1 = *(const ulonglong2*)(br + 4);
            unsigned long long av[8];
            av[0] = bcast2(a0.x); av[1] = bcast2(a0.y); av[2] = bcast2(a0.z); av[3] = bcast2(a0.w);
            av[4] = bcast2(a1.x); av[5] = bcast2(a1.y); av[6] = bcast2(a1.z); av[7] = bcast2(a1.w);
            unsigned long long bv[4] = {bq0.x, bq0.y, bq1.x, bq1.y};
            #pragma unroll
            for (int mi = 0; mi < 8; mi++)
                #pragma unroll
                for (int pj = 0; pj < 4; pj++)
                    fma2(acc[mi][pj], av[mi], bv[pj]);
        }
        __syncthreads();
    }

    // ---- epilogue 1: relu(acc + b1) -> h1s transposed [k=n][m] ----
    {
        float4 bl = *(const float4*)(b1 + nb);
        float4 bh = *(const float4*)(b1 + nb + 4);
        float bb1[8] = {bl.x, bl.y, bl.z, bl.w, bh.x, bh.y, bh.z, bh.w};
        #pragma unroll
        for (int nj = 0; nj < 8; nj++) {
            float4 v0, v1;
            float* p0 = (float*)&v0; float* p1 = (float*)&v1;
            #pragma unroll
            for (int mi = 0; mi < 8; mi++) {
                unsigned long long a = acc[mi][nj >> 1];
                float t = (nj & 1) ? hi32(a) : lo32(a);
                t = fmaxf(t + bb1[nj], 0.0f);
                if (mi < 4) p0[mi] = t; else p1[mi - 4] = t;
            }
            *(float4*)(h1s + (nb + nj) * LDA + mb)     = v0;
            *(float4*)(h1s + (nb + nj) * LDA + mb + 4) = v1;
        }
    }

    #pragma unroll
    for (int i = 0; i < 8; i++)
        #pragma unroll
        for (int j = 0; j < 4; j++) acc[i][j] = 0ull;

    // ================= GEMM2: K = 128 in 4 chunks of 32 =================
    for (int kc = 0; kc < 4; kc++) {
        const int k0 = kc * 32;
        #pragma unroll 4
        for (int it = 0; it < 16; it++) {
            int n = it * 8 + warp;
            Bs[lane * LDA + n] = W2[n * HID + k0 + lane];
        }
        __syncthreads();   // orders h1s epilogue writes (first iter) + Bs loads before math
        #pragma unroll 4
        for (int kk = 0; kk < 32; kk++) {
            const float* ar = h1s + (k0 + kk) * LDA + mb;
            float4 a0 = *(const float4*)ar;
            float4 a1 = *(const float4*)(ar + 4);
            const float* br = Bs + kk * LDA + nb;
            ulonglong2 bq0 = *(const ulonglong2*)br;
            ulonglong2 bq1 = *(const ulonglong2*)(br + 4);
            unsigned long long av[8];
            av[0] = bcast2(a0.x); av[1] = bcast2(a0.y); av[2] = bcast2(a0.z); av[3] = bcast2(a0.w);
            av[4] = bcast2(a1.x); av[5] = bcast2(a1.y); av[6] = bcast2(a1.z); av[7] = bcast2(a1.w);
            unsigned long long bv[4] = {bq0.x, bq0.y, bq1.x, bq1.y};
            #pragma unroll
            for (int mi = 0; mi < 8; mi++)
                #pragma unroll
                for (int pj = 0; pj < 4; pj++)
                    fma2(acc[mi][pj], av[mi], bv[pj]);
        }
        __syncthreads();
    }

    // ---- epilogue 2: relu(acc + b2) -> out ----
    {
        float4 bl = *(const float4*)(b2 + nb);
        float4 bh = *(const float4*)(b2 + nb + 4);
        float bb2[8] = {bl.x, bl.y, bl.z, bl.w, bh.x, bh.y, bh.z, bh.w};
        #pragma unroll
        for (int mi = 0; mi < 8; mi++) {
            int m = m0 + mb + mi;
            if (m < NN) {
                float4 v0, v1;
                float* p0 = (float*)&v0; float* p1 = (float*)&v1;
                #pragma unroll
                for (int nj = 0; nj < 8; nj++) {
                    unsigned long long a = acc[mi][nj >> 1];
                    float t = (nj & 1) ? hi32(a) : lo32(a);
                    t = fmaxf(t + bb2[nj], 0.0f);
                    if (nj < 4) p0[nj] = t; else p1[nj - 4] = t;
                }
                *(float4*)(out + (size_t)m * HID + nb)     = v0;
                *(float4*)(out + (size_t)m * HID + nb + 4) = v1;
            }
        }
    }
}

// ---------------- launch ----------------
extern "C" void kernel_launch(void* const* d_in, const int* in_sizes, int n_in,
                              void* d_out, int out_size)
{
    const float* verts = (const float*)d_in[0];
    const float* bb    = (const float*)d_in[1];
    const float* seg   = (const float*)d_in[2];
    const void*  edges = d_in[3];
    const float* W1    = (const float*)d_in[4];
    const float* b1    = (const float*)d_in[5];
    const float* W2    = (const float*)d_in[6];
    const float* b2    = (const float*)d_in[7];
    float* out = (float*)d_out;

    k_detect<<<1, 32>>>((const int*)edges);
    k_zero<<<(NN + 255) / 256, 256>>>();
    k_transpose<<<dim3(16, NPIX / 32), dim3(32, 8)>>>(bb, seg);
    k_degree<<<2048, 256>>>(edges);
    k_max<<<(NN + 255) / 256, 256>>>();

    size_t smem = (size_t)SMEM_FLOATS * sizeof(float);   // 90624 B
    cudaFuncSetAttribute(k_main, cudaFuncAttributeMaxDynamicSharedMemorySize, (int)smem);
    k_main<<<(NN + 127) / 128, 256, smem>>>(verts, W1, b1, W2, b2, out);
}

// round 5
// speedup vs baseline: 2.0121x; 1.2827x over previous
#include <cuda_runtime.h>
#include <math.h>

// ---------------- problem constants ----------------
#define NN     200000
#define NEDGE  800000
#define CBB    480
#define CT     484
#define FDIM   128
#define NPIX   (FDIM*FDIM)
#define HID    128
#define KIN    488
#define LDA    132                  // A/h1 row stride: lane*132+4q -> conflict-free STS.128 / LDS.128
#define LDB    140                  // B row stride with hole layout
#define A_BUF  (32*LDA)
#define B_OFF  (128*LDA)            // h1 region is 128 rows (GEMM2); GEMM1 uses rows 0..63 as 2 bufs
#define B_BUF  (32*LDB)
#define PQ_OFF (B_OFF + 2*B_BUF)    // int4[128]
#define WQ_OFF (PQ_OFF + 512)       // float4[128] bilinear weights
#define SQ_OFF (WQ_OFF + 512)       // float4[128] scalar feats
#define SMEM_FLOATS (SQ_OFF + 512)
// group g (8 floats) gets a 16B hole every 4 groups -> conflict-free B math loads
#define BOFF(G) ((G)*8 + ((G)>>2)*4)

// ---------------- device scratch ----------------
__device__ float g_ft[(size_t)NPIX * CT];   // (pixel, channel) feature map, L2-resident
__device__ float g_W1p[512*HID];            // permuted zero-padded k-major W1
__device__ float g_W2p[HID*HID];            // transposed W2
__device__ int   g_deg[NN];
__device__ int   g_maxdeg;
__device__ int   g_e64;

// ---------------- packed f32x2 helpers ----------------
__device__ __forceinline__ void fma2(unsigned long long& d, unsigned long long a, unsigned long long b) {
    asm("fma.rn.f32x2 %0, %1, %2, %0;" : "+l"(d) : "l"(a), "l"(b));
}
__device__ __forceinline__ unsigned long long bcast2(float a) {
    unsigned long long r;
    asm("mov.b64 %0, {%1, %1};" : "=l"(r) : "r"(__float_as_uint(a)));
    return r;
}
__device__ __forceinline__ float lo32(unsigned long long v) { return __uint_as_float((unsigned)v); }
__device__ __forceinline__ float hi32(unsigned long long v) { return __uint_as_float((unsigned)(v >> 32)); }
__device__ __forceinline__ void cp16(float* s, const float* g) {
    unsigned ss = (unsigned)__cvta_generic_to_shared(s);
    asm volatile("cp.async.cg.shared.global [%0], [%1], 16;" :: "r"(ss), "l"(g));
}

// ---------------- prep kernels ----------------
__global__ void k_init(const int* __restrict__ e) {
    int i = blockIdx.x * blockDim.x + threadIdx.x;
    if (i < NN) g_deg[i] = 0;
    if (blockIdx.x == 0) {
        if (threadIdx.x < 32) {
            int nz = (e[2 * threadIdx.x + 1] != 0) ? 1 : 0;
            unsigned m = __ballot_sync(0xffffffffu, nz);
            if (threadIdx.x == 0) { g_e64 = (m == 0u) ? 1 : 0; g_maxdeg = 0; }
        }
    }
}

__global__ void k_degree(const void* __restrict__ eptr) {
    const int total = 2 * NEDGE;
    const bool is64 = (g_e64 != 0);
    const long long* __restrict__ e64 = (const long long*)eptr;
    const int* __restrict__ e32 = (const int*)eptr;
    for (int i = blockIdx.x * blockDim.x + threadIdx.x; i < total; i += gridDim.x * blockDim.x) {
        int idx = is64 ? (int)e64[i] : e32[i];
        atomicAdd(&g_deg[idx], 1);
    }
}

__global__ void k_max() {
    int i = blockIdx.x * blockDim.x + threadIdx.x;
    int v = (i < NN) ? g_deg[i] : 0;
    #pragma unroll
    for (int o = 16; o > 0; o >>= 1) v = max(v, __shfl_down_sync(0xffffffffu, v, o));
    if ((threadIdx.x & 31) == 0) atomicMax(&g_maxdeg, v);
}

__global__ void k_wperm(const float* __restrict__ W1, const float* __restrict__ W2) {
    int r = blockIdx.x, n = threadIdx.x;
    if (r < 512) {
        int col;
        if      (r < CT)   col = r + 2;   // channels (backbone+seg) -> W1 cols 2..485
        else if (r == 484) col = 0;       // coord x
        else if (r == 485) col = 1;       // coord y
        else if (r == 486) col = 486;     // degree_norm
        else if (r == 487) col = 487;     // dist_to_boundary
        else               col = -1;      // zero pad
        g_W1p[r * HID + n] = (col >= 0) ? W1[n * KIN + col] : 0.0f;
    } else {
        int k = r - 512;
        g_W2p[k * HID + n] = W2[n * HID + k];
    }
}

__global__ void k_transpose(const float* __restrict__ bb, const float* __restrict__ seg) {
    __shared__ float t[32][33];
    const int tx = threadIdx.x, ty = threadIdx.y;   // 32 x 8
    const int c0 = blockIdx.x * 32, p0 = blockIdx.y * 32;
    #pragma unroll
    for (int i = 0; i < 4; i++) {
        int c = c0 + ty + i * 8;
        float v = 0.0f;
        if (c < CT)
            v = (c < CBB) ? bb[(size_t)c * NPIX + p0 + tx]
                          : seg[(size_t)(c - CBB) * NPIX + p0 + tx];
        t[ty + i * 8][tx] = v;
    }
    __syncthreads();
    #pragma unroll
    for (int i = 0; i < 4; i++) {
        int p = p0 + ty + i * 8;
        int c = c0 + tx;
        if (c < CT) g_ft[(size_t)p * CT + c] = t[tx][ty + i * 8];
    }
}

// ---------------- build helpers ----------------
// one quad = 4 nodes; thread (warp,lane) builds A[k=lane][m=quad*4..+3]
__device__ __forceinline__ void gather_issue(const int4* __restrict__ Pq, int quad, int kp,
                                             float* __restrict__ f) {
    if (kp < CT) {
        const float* __restrict__ base = g_ft + kp;
        #pragma unroll
        for (int i = 0; i < 4; i++) {
            int4 q = Pq[quad * 4 + i];          // lanes read same pixels, consecutive channels -> coalesced
            f[i * 4 + 0] = base[q.x];
            f[i * 4 + 1] = base[q.y];
            f[i * 4 + 2] = base[q.z];
            f[i * 4 + 3] = base[q.w];
        }
    }
}

__device__ __forceinline__ void gather_store(const float4* __restrict__ Wq, const float4* __restrict__ Sq,
        int quad, int kp, int lane, const float* __restrict__ f, float* __restrict__ bufA) {
    float4 v;
    #pragma unroll
    for (int i = 0; i < 4; i++) {
        int m = quad * 4 + i;
        float r;
        if (kp < CT) {
            float4 w = Wq[m];
            r = w.x * f[i*4+0] + w.y * f[i*4+1] + w.z * f[i*4+2] + w.w * f[i*4+3];
        } else if (kp < KIN) {
            float4 s = Sq[m];
            r = (&s.x)[kp - CT];
        } else {
            r = 0.0f;
        }
        (&v.x)[i] = r;
    }
    *(float4*)(bufA + lane * LDA + quad * 4) = v;   // conflict-free STS.128
}

__device__ __forceinline__ void b_async(const float* __restrict__ Wsrc, int k0, int tid,
                                        float* __restrict__ bufB) {
    int k = tid >> 3, j = tid & 7;                  // k row 0..31, 16-float slab j
    const float* src = Wsrc + (size_t)(k0 + k) * HID + j * 16;
    float* row = bufB + k * LDB;
    int g0 = j * 2;
    cp16(row + BOFF(g0),     src);
    cp16(row + BOFF(g0) + 4, src + 4);
    cp16(row + BOFF(g0+1),     src + 8);
    cp16(row + BOFF(g0+1) + 4, src + 12);
}

__device__ __forceinline__ void math_8(const float* __restrict__ A, const float* __restrict__ B,
        int mb, int boff, unsigned long long (&acc)[8][4]) {
    #pragma unroll
    for (int kk = 0; kk < 8; kk++) {
        float4 a0 = *(const float4*)(A + kk * LDA + mb);
        float4 a1 = *(const float4*)(A + kk * LDA + mb + 4);
        const float* br = B + kk * LDB + boff;
        ulonglong2 q0 = *(const ulonglong2*)br;
        ulonglong2 q1 = *(const ulonglong2*)(br + 4);
        float av[8] = {a0.x, a0.y, a0.z, a0.w, a1.x, a1.y, a1.z, a1.w};
        #pragma unroll
        for (int mi = 0; mi < 8; mi++) {
            unsigned long long am = bcast2(av[mi]);
            fma2(acc[mi][0], am, q0.x);
            fma2(acc[mi][1], am, q0.y);
            fma2(acc[mi][2], am, q1.x);
            fma2(acc[mi][3], am, q1.y);
        }
    }
}

// ---------------- fused gather + MLP ----------------
__global__ void __launch_bounds__(256, 2) k_main(
    const float* __restrict__ verts,
    const float* __restrict__ b1,
    const float* __restrict__ b2,
    float* __restrict__ out)
{
    extern __shared__ float sm[];
    float*  h1s = sm;                       // GEMM1: A double buffer (rows 0..63); GEMM2: full h1^T
    float*  Bsm = sm + B_OFF;
    int4*   Pq  = (int4*)(sm + PQ_OFF);
    float4* Wq  = (float4*)(sm + WQ_OFF);
    float4* Sq  = (float4*)(sm + SQ_OFF);

    const int tid = threadIdx.x;
    const int m0 = blockIdx.x * 128;

    if (tid < 128) {
        int node = min(m0 + tid, NN - 1);
        float vx = verts[2 * node], vy = verts[2 * node + 1];
        float ix = vx * (127.0f / 512.0f), iy = vy * (127.0f / 512.0f);
        float fx = floorf(ix), fy = floorf(iy);
        float wx = ix - fx, wy = iy - fy;
        int x0 = min(max((int)fx, 0), FDIM - 1);
        int x1 = min(x0 + 1, FDIM - 1);
        int y0 = min(max((int)fy, 0), FDIM - 1);
        int y1 = min(y0 + 1, FDIM - 1);
        Pq[tid] = make_int4((y0 * FDIM + x0) * CT, (y0 * FDIM + x1) * CT,
                            (y1 * FDIM + x0) * CT, (y1 * FDIM + x1) * CT);
        Wq[tid] = make_float4((1.0f - wx) * (1.0f - wy), wx * (1.0f - wy),
                              (1.0f - wx) * wy, wx * wy);
        float dg = (float)g_deg[node] / ((float)g_maxdeg + 1e-6f);
        float dx = fminf(vx, 512.0f - vx), dy = fminf(vy, 512.0f - vy);
        Sq[tid] = make_float4(vx * (1.0f / 512.0f), vy * (1.0f / 512.0f),
                              dg, fminf(dx, dy) * (1.0f / 256.0f));
    }

    const int warp = tid >> 5, lane = tid & 31;
    const int wm = warp & 3, wn = warp >> 2;        // 4x2 warp grid
    const int mb = wm * 32 + (lane >> 3) * 8;       // 8 contiguous m
    const int G  = wn * 8 + (lane & 7);             // B group
    const int boff = BOFF(G);
    const int nb = G * 8;

    __syncthreads();

    unsigned long long acc[8][4];
    #pragma unroll
    for (int i = 0; i < 8; i++)
        #pragma unroll
        for (int j = 0; j < 4; j++) acc[i][j] = 0ull;

    float f[16];

    // -------- prologue: build chunk 0 into buffer 0 --------
    b_async(g_W1p, 0, tid, Bsm);
    asm volatile("cp.async.commit_group;");
    #pragma unroll
    for (int s = 0; s < 4; s++) {
        gather_issue(Pq, warp + 8 * s, lane, f);
        gather_store(Wq, Sq, warp + 8 * s, lane, lane, f, h1s);
    }
    asm volatile("cp.async.wait_group 0;");
    __syncthreads();

    // ================= GEMM1: 16 chunks of 32 =================
    #pragma unroll 1
    for (int kc = 0; kc < 16; kc++) {
        const float* A = h1s + (kc & 1) * A_BUF;
        const float* B = Bsm + (kc & 1) * B_BUF;
        float* An = h1s + ((kc + 1) & 1) * A_BUF;
        float* Bn = Bsm + ((kc + 1) & 1) * B_BUF;
        const int kpn = (kc + 1) * 32 + lane;
        const bool more = (kc < 15);

        if (more) b_async(g_W1p, (kc + 1) * 32, tid, Bn);
        else      b_async(g_W2p, 0, tid, Bn);          // prefetch W2 chunk 0
        asm volatile("cp.async.commit_group;");

        #pragma unroll
        for (int s = 0; s < 4; s++) {
            if (more) gather_issue(Pq, warp + 8 * s, kpn, f);
            math_8(A + s * 8 * LDA, B + s * 8 * LDB, mb, boff, acc);
            if (more) gather_store(Wq, Sq, warp + 8 * s, kpn, lane, f, An);
        }
        asm volatile("cp.async.wait_group 0;");
        __syncthreads();
    }

    // -------- epilogue 1: relu(acc + b1) -> h1s transposed [n][m] --------
    {
        float4 bl = *(const float4*)(b1 + nb);
        float4 bh = *(const float4*)(b1 + nb + 4);
        float bias[8] = {bl.x, bl.y, bl.z, bl.w, bh.x, bh.y, bh.z, bh.w};
        #pragma unroll
        for (int nj = 0; nj < 8; nj++) {
            float4 v0, v1;
            #pragma unroll
            for (int mi = 0; mi < 8; mi++) {
                unsigned long long a = acc[mi][nj >> 1];
                float t = (nj & 1) ? hi32(a) : lo32(a);
                t = fmaxf(t + bias[nj], 0.0f);
                if (mi < 4) (&v0.x)[mi] = t; else (&v1.x)[mi - 4] = t;
            }
            *(float4*)(h1s + (nb + nj) * LDA + mb)     = v0;
            *(float4*)(h1s + (nb + nj) * LDA + mb + 4) = v1;
        }
    }
    #pragma unroll
    for (int i = 0; i < 8; i++)
        #pragma unroll
        for (int j = 0; j < 4; j++) acc[i][j] = 0ull;
    __syncthreads();

    // ================= GEMM2: 4 chunks of 32 =================
    #pragma unroll 1
    for (int kc = 0; kc < 4; kc++) {
        const float* A = h1s + kc * 32 * LDA;
        const float* B = Bsm + (kc & 1) * B_BUF;
        if (kc < 3) {
            b_async(g_W2p, (kc + 1) * 32, tid, Bsm + ((kc + 1) & 1) * B_BUF);
            asm volatile("cp.async.commit_group;");
        }
        #pragma unroll
        for (int s = 0; s < 4; s++)
            math_8(A + s * 8 * LDA, B + s * 8 * LDB, mb, boff, acc);
        asm volatile("cp.async.wait_group 0;");
        __syncthreads();
    }

    // -------- epilogue 2: relu(acc + b2) -> out --------
    {
        float4 bl = *(const float4*)(b2 + nb);
        float4 bh = *(const float4*)(b2 + nb + 4);
        float bias[8] = {bl.x, bl.y, bl.z, bl.w, bh.x, bh.y, bh.z, bh.w};
        #pragma unroll
        for (int mi = 0; mi < 8; mi++) {
            int m = m0 + mb + mi;
            if (m < NN) {
                float4 v0, v1;
                #pragma unroll
                for (int nj = 0; nj < 8; nj++) {
                    unsigned long long a = acc[mi][nj >> 1];
                    float t = (nj & 1) ? hi32(a) : lo32(a);
                    t = fmaxf(t + bias[nj], 0.0f);
                    if (nj < 4) (&v0.x)[nj] = t; else (&v1.x)[nj - 4] = t;
                }
                *(float4*)(out + (size_t)m * HID + nb)     = v0;
                *(float4*)(out + (size_t)m * HID + nb + 4) = v1;
            }
        }
    }
}

// ---------------- launch ----------------
extern "C" void kernel_launch(void* const* d_in, const int* in_sizes, int n_in,
                              void* d_out, int out_size)
{
    const float* verts = (const float*)d_in[0];
    const float* bb    = (const float*)d_in[1];
    const float* seg   = (const float*)d_in[2];
    const void*  edges = d_in[3];
    const float* W1    = (const float*)d_in[4];
    const float* b1    = (const float*)d_in[5];
    const float* W2    = (const float*)d_in[6];
    const float* b2    = (const float*)d_in[7];
    float* out = (float*)d_out;

    k_init<<<(NN + 255) / 256, 256>>>((const int*)edges);
    k_wperm<<<640, 128>>>(W1, W2);
    k_transpose<<<dim3(16, NPIX / 32), dim3(32, 8)>>>(bb, seg);
    k_degree<<<2048, 256>>>(edges);
    k_max<<<(NN + 255) / 256, 256>>>();

    size_t smem = (size_t)SMEM_FLOATS * sizeof(float);   // 109568 B
    cudaFuncSetAttribute(k_main, cudaFuncAttributeMaxDynamicSharedMemorySize, (int)smem);
    k_main<<<(NN + 127) / 128, 256, smem>>>(verts, b1, b2, out);
}

// round 7
// speedup vs baseline: 3.6117x; 1.7950x over previous
#include <cuda_runtime.h>
#include <cuda_bf16.h>
#include <math.h>
#include <stdint.h>

// ---------------- problem constants ----------------
#define NN     200000
#define NEDGE  800000
#define CBB    480
#define CT     484
#define FDIM   128
#define NPIX   (FDIM*FDIM)
#define HID    128
#define KIN    488

// ---------------- smem layout (bytes) ----------------
// GEMM1 tiles: A/B are [128 rows][32 k] bf16, row stride 40 bf16 = 80B (conflict-free frags)
#define TILE1    10240                  // 128*80
#define A1_OFF(b)   ((b)*2*TILE1)       // hi at +0, lo at +TILE1
#define B1_OFF(b)   (40960 + (b)*2*TILE1)
#define A2_STR   272                    // h1 tile row stride bytes (136 bf16)
#define A2H_OFF  0                      // overlaps GEMM1 tiles (used after GEMM1)
#define A2L_OFF  34816
#define B2_OFF   81920                  // single buffer: hi +0, lo +TILE1
#define PQ_OFF   102400                 // int4[128]
#define WQ_OFF   104448                 // float4[128]
#define SQ_OFF   106496                 // float4[128]
#define SMEM_BYTES 108544

// ---------------- device scratch ----------------
__device__ float g_ft[(size_t)NPIX * CT];     // (pixel, channel) fp32 feature map (~31.7MB)
__device__ __nv_bfloat16 g_W1h[128*512];      // [n][k'=512] hi
__device__ __nv_bfloat16 g_W1l[128*512];      // lo
__device__ __nv_bfloat16 g_W2h[128*128];      // [n][k=128] hi
__device__ __nv_bfloat16 g_W2l[128*128];
__device__ int g_deg[NN];
__device__ int g_maxdeg;
__device__ int g_e64;

// ---------------- helpers ----------------
__device__ __forceinline__ void cp16(void* s, const void* g) {
    unsigned ss = (unsigned)__cvta_generic_to_shared(s);
    asm volatile("cp.async.cg.shared.global [%0], [%1], 16;" :: "r"(ss), "l"(g));
}
#define CP_COMMIT() asm volatile("cp.async.commit_group;")
#define CP_WAIT0()  asm volatile("cp.async.wait_group 0;" ::: "memory")

__device__ __forceinline__ void mma16816(float* d, const uint32_t* a, uint32_t b0, uint32_t b1) {
    asm("mma.sync.aligned.m16n8k16.row.col.f32.bf16.bf16.f32 "
        "{%0,%1,%2,%3}, {%4,%5,%6,%7}, {%8,%9}, {%0,%1,%2,%3};"
        : "+f"(d[0]), "+f"(d[1]), "+f"(d[2]), "+f"(d[3])
        : "r"(a[0]), "r"(a[1]), "r"(a[2]), "r"(a[3]), "r"(b0), "r"(b1));
}

__device__ __forceinline__ void ldfragA(uint32_t* a, const char* base, int row, int kb, int str) {
    a[0] = *(const uint32_t*)(base + row * str + kb);
    a[1] = *(const uint32_t*)(base + (row + 8) * str + kb);
    a[2] = *(const uint32_t*)(base + row * str + kb + 16);
    a[3] = *(const uint32_t*)(base + (row + 8) * str + kb + 16);
}

// one eighth of a 32-k chunk: k16 = s>>2, nb pair = (s&3)*2..+1
__device__ __forceinline__ void math_eighth(
    const char* Ah, const char* Al, const char* Bh, const char* Bl,
    int s, int wM, int wN, int g, int tc, int strA,
    uint32_t (&ah)[2][4], uint32_t (&al)[2][4], float (&acc)[2][8][4])
{
    int kb = ((s >> 2) * 16 + tc) * 2;
    if ((s & 3) == 0) {
        ldfragA(ah[0], Ah, wM + g,      kb, strA);
        ldfragA(ah[1], Ah, wM + 16 + g, kb, strA);
        ldfragA(al[0], Al, wM + g,      kb, strA);
        ldfragA(al[1], Al, wM + 16 + g, kb, strA);
    }
    #pragma unroll
    for (int i = 0; i < 2; i++) {
        int nb = (s & 3) * 2 + i;
        const char* bhp = Bh + (wN + nb * 8 + g) * 80 + kb;
        const char* blp = Bl + (wN + nb * 8 + g) * 80 + kb;
        uint32_t bh0 = *(const uint32_t*)bhp, bh1 = *(const uint32_t*)(bhp + 16);
        uint32_t bl0 = *(const uint32_t*)blp, bl1 = *(const uint32_t*)(blp + 16);
        #pragma unroll
        for (int mb = 0; mb < 2; mb++) {
            mma16816(acc[mb][nb], ah[mb], bh0, bh1);
            mma16816(acc[mb][nb], ah[mb], bl0, bl1);
            mma16816(acc[mb][nb], al[mb], bh0, bh1);
        }
    }
}

__device__ __forceinline__ void bld_issue(const int4* __restrict__ Pq, int m, int k, float2* f) {
    if (k < CT) {
        int4 q = Pq[m];
        const float* __restrict__ ft = g_ft;
        f[0] = *(const float2*)(ft + q.x + k);
        f[1] = *(const float2*)(ft + q.y + k);
        f[2] = *(const float2*)(ft + q.z + k);
        f[3] = *(const float2*)(ft + q.w + k);
    }
}

__device__ __forceinline__ void bld_store(const float4* __restrict__ Wq, const float4* __restrict__ Sq,
        int m, int k, const float2* f, char* aH, char* aL, int kofs) {
    float v0, v1;
    if (k < CT) {
        float4 w = Wq[m];
        v0 = w.x * f[0].x + w.y * f[1].x + w.z * f[2].x + w.w * f[3].x;
        v1 = w.x * f[0].y + w.y * f[1].y + w.z * f[2].y + w.w * f[3].y;
    } else if (k == 484) { float4 s = Sq[m]; v0 = s.x; v1 = s.y; }
    else if (k == 486)   { float4 s = Sq[m]; v0 = s.z; v1 = s.w; }
    else { v0 = 0.0f; v1 = 0.0f; }
    uint32_t hw, lw;
    asm("cvt.rn.bf16x2.f32 %0, %1, %2;" : "=r"(hw) : "f"(v1), "f"(v0));   // lo=v0, hi=v1
    float l0 = v0 - __uint_as_float(hw << 16);
    float l1 = v1 - __uint_as_float(hw & 0xffff0000u);
    asm("cvt.rn.bf16x2.f32 %0, %1, %2;" : "=r"(lw) : "f"(l1), "f"(l0));
    *(uint32_t*)(aH + m * 80 + kofs) = hw;
    *(uint32_t*)(aL + m * 80 + kofs) = lw;
}

__device__ __forceinline__ void b1fill(int c, char* dstH, int tid) {
    int r = tid >> 1, seg = (tid & 1) * 2;
    const char* sh = (const char*)g_W1h + r * 1024 + c * 64 + seg * 16;
    const char* sl = (const char*)g_W1l + r * 1024 + c * 64 + seg * 16;
    char* dh = dstH + r * 80 + seg * 16;
    char* dl = dstH + TILE1 + r * 80 + seg * 16;
    cp16(dh, sh); cp16(dh + 16, sh + 16);
    cp16(dl, sl); cp16(dl + 16, sl + 16);
}
__device__ __forceinline__ void b2fill(int c, char* dstH, int tid) {
    int r = tid >> 1, seg = (tid & 1) * 2;
    const char* sh = (const char*)g_W2h + r * 256 + c * 64 + seg * 16;
    const char* sl = (const char*)g_W2l + r * 256 + c * 64 + seg * 16;
    char* dh = dstH + r * 80 + seg * 16;
    char* dl = dstH + TILE1 + r * 80 + seg * 16;
    cp16(dh, sh); cp16(dh + 16, sh + 16);
    cp16(dl, sl); cp16(dl + 16, sl + 16);
}

// ---------------- prep kernels ----------------
#define PB_Z   782
#define PB_W1  (PB_Z + 128)
#define PB_W2  (PB_W1 + 64)
#define PB_T   (PB_W2 + 8192)

__global__ void k_prep(const int* __restrict__ e,
                       const float* __restrict__ W1, const float* __restrict__ W2,
                       const float* __restrict__ bb, const float* __restrict__ seg) {
    int bx = blockIdx.x, tid = threadIdx.x;
    if (bx < PB_Z) {
        int i = bx * 256 + tid;
        if (i < NN) g_deg[i] = 0;
        if (bx == 0 && tid < 32) {
            int nz = (e[2 * tid + 1] != 0) ? 1 : 0;
            unsigned m = __ballot_sync(0xffffffffu, nz);
            if (tid == 0) { g_e64 = (m == 0u) ? 1 : 0; g_maxdeg = 0; }
        }
    } else if (bx < PB_W1) {
        int n = bx - PB_Z;
        #pragma unroll
        for (int it = 0; it < 2; it++) {
            int r = it * 256 + tid;
            int col;
            if      (r < CT)   col = r + 2;
            else if (r == 484) col = 0;
            else if (r == 485) col = 1;
            else if (r == 486) col = 486;
            else if (r == 487) col = 487;
            else               col = -1;
            float v = (col >= 0) ? W1[n * KIN + col] : 0.0f;
            __nv_bfloat16 h = __float2bfloat16(v);
            g_W1h[n * 512 + r] = h;
            g_W1l[n * 512 + r] = __float2bfloat16(v - __bfloat162float(h));
        }
    } else if (bx < PB_W2) {
        int n = (bx - PB_W1) * 2 + (tid >> 7), k = tid & 127;
        float v = W2[n * HID + k];
        __nv_bfloat16 h = __float2bfloat16(v);
        g_W2h[n * 128 + k] = h;
        g_W2l[n * 128 + k] = __float2bfloat16(v - __bfloat162float(h));
    } else {
        __shared__ float t[32][33];
        int i = bx - PB_W2;
        int c0 = (i & 15) * 32, p0 = (i >> 4) * 32;
        int tx = tid & 31, ty = tid >> 5;    // 32 x 8
        #pragma unroll
        for (int q = 0; q < 4; q++) {
            int c = c0 + ty + q * 8;
            float v = 0.0f;
            if (c < CT)
                v = (c < CBB) ? bb[(size_t)c * NPIX + p0 + tx]
                              : seg[(size_t)(c - CBB) * NPIX + p0 + tx];
            t[ty + q * 8][tx] = v;
        }
        __syncthreads();
        #pragma unroll
        for (int q = 0; q < 4; q++) {
            int p = p0 + ty + q * 8;
            int c = c0 + tx;
            if (c < CT) g_ft[(size_t)p * CT + c] = t[tx][ty + q * 8];
        }
    }
}

__global__ void k_degree(const void* __restrict__ eptr) {
    const int total = 2 * NEDGE;
    const bool is64 = (g_e64 != 0);
    const long long* __restrict__ e64 = (const long long*)eptr;
    const int* __restrict__ e32 = (const int*)eptr;
    for (int i = blockIdx.x * blockDim.x + threadIdx.x; i < total; i += gridDim.x * blockDim.x) {
        int idx = is64 ? (int)e64[i] : e32[i];
        atomicAdd(&g_deg[idx], 1);
    }
}

__global__ void k_max() {
    int i = blockIdx.x * blockDim.x + threadIdx.x;
    int v = (i < NN) ? g_deg[i] : 0;
    #pragma unroll
    for (int o = 16; o > 0; o >>= 1) v = max(v, __shfl_down_sync(0xffffffffu, v, o));
    if ((threadIdx.x & 31) == 0) atomicMax(&g_maxdeg, v);
}

// ---------------- main: gather + bf16-split mma.sync MLP ----------------
__global__ void __launch_bounds__(256, 2) k_main(
    const float* __restrict__ verts,
    const float* __restrict__ b1,
    const float* __restrict__ b2,
    float* __restrict__ out)
{
    extern __shared__ char smem[];
    int4*   Pq = (int4*)(smem + PQ_OFF);
    float4* Wq = (float4*)(smem + WQ_OFF);
    float4* Sq = (float4*)(smem + SQ_OFF);

    const int tid = threadIdx.x;
    const int m0 = blockIdx.x * 128;

    // per-node params
    if (tid < 128) {
        int node = min(m0 + tid, NN - 1);
        float vx = verts[2 * node], vy = verts[2 * node + 1];
        float ix = vx * (127.0f / 512.0f), iy = vy * (127.0f / 512.0f);
        float fx = floorf(ix), fy = floorf(iy);
        float wx = ix - fx, wy = iy - fy;
        int x0 = min(max((int)fx, 0), FDIM - 1);
        int x1 = min(x0 + 1, FDIM - 1);
        int y0 = min(max((int)fy, 0), FDIM - 1);
        int y1 = min(y0 + 1, FDIM - 1);
        Pq[tid] = make_int4((y0 * FDIM + x0) * CT, (y0 * FDIM + x1) * CT,
                            (y1 * FDIM + x0) * CT, (y1 * FDIM + x1) * CT);
        Wq[tid] = make_float4((1.0f - wx) * (1.0f - wy), wx * (1.0f - wy),
                              (1.0f - wx) * wy, wx * wy);
        float dg = (float)g_deg[node] / ((float)g_maxdeg + 1e-6f);
        float dx = fminf(vx, 512.0f - vx), dy = fminf(vy, 512.0f - vy);
        Sq[tid] = make_float4(vx * (1.0f / 512.0f), vy * (1.0f / 512.0f),
                              dg, fminf(dx, dy) * (1.0f / 256.0f));
    }
    __syncthreads();

    const int warp = tid >> 5, lane = tid & 31;
    const int g  = lane >> 2, tc = (lane & 3) * 2;    // mma quad group / k-pair
    const int wM = (warp & 3) * 32, wN = (warp >> 2) * 64;
    const int wp   = warp * 2 + (lane >> 4);          // builder m sub-index
    const int kp2  = (lane & 15) * 2;                 // builder k-pair within chunk
    const int kofs = (lane & 15) * 4;                 // builder store byte offset

    float acc[2][8][4];
    #pragma unroll
    for (int a = 0; a < 2; a++)
        #pragma unroll
        for (int b = 0; b < 8; b++)
            #pragma unroll
            for (int c = 0; c < 4; c++) acc[a][b][c] = 0.0f;

    // -------- prologue: B chunk0 via cp.async, A chunk0 built --------
    b1fill(0, smem + B1_OFF(0), tid);
    CP_COMMIT();
    #pragma unroll
    for (int it = 0; it < 8; it++) {
        float2 f[4];
        int m = it * 16 + wp;
        bld_issue(Pq, m, kp2, f);
        bld_store(Wq, Sq, m, kp2, f, smem + A1_OFF(0), smem + A1_OFF(0) + TILE1, kofs);
    }
    CP_WAIT0();
    __syncthreads();

    // ================= GEMM1: 16 chunks of 32 =================
    #pragma unroll 1
    for (int c = 0; c < 16; c++) {
        const int buf = c & 1, nxt = buf ^ 1;
        const char* Ah = smem + A1_OFF(buf);
        const char* Al = Ah + TILE1;
        const char* Bh = smem + B1_OFF(buf);
        const char* Bl = Bh + TILE1;
        char* nAh = smem + A1_OFF(nxt);
        char* nAl = nAh + TILE1;
        const bool more = (c < 15);

        if (more) b1fill(c + 1, smem + B1_OFF(nxt), tid);
        else      b2fill(0, smem + B2_OFF, tid);       // prefetch W2 chunk 0
        CP_COMMIT();

        uint32_t ah[2][4], al[2][4];
        const int kn = (c + 1) * 32 + kp2;
        #pragma unroll
        for (int s = 0; s < 8; s++) {
            float2 f[4];
            const int m = s * 16 + wp;
            if (more) bld_issue(Pq, m, kn, f);
            math_eighth(Ah, Al, Bh, Bl, s, wM, wN, g, tc, 80, ah, al, acc);
            if (more) bld_store(Wq, Sq, m, kn, f, nAh, nAl, kofs);
        }
        CP_WAIT0();
        __syncthreads();
    }

    // -------- epilogue 1: h1 = relu(D1 + b1) -> bf16 hi/lo smem tile --------
    {
        char* A2h = smem + A2H_OFF;
        char* A2l = smem + A2L_OFF;
        #pragma unroll
        for (int mb = 0; mb < 2; mb++) {
            int row = wM + mb * 16 + g;
            #pragma unroll
            for (int nb = 0; nb < 8; nb++) {
                int col = wN + nb * 8 + tc;
                float2 bb = *(const float2*)(b1 + col);
                float v0 = fmaxf(acc[mb][nb][0] + bb.x, 0.0f);
                float v1 = fmaxf(acc[mb][nb][1] + bb.y, 0.0f);
                float v2 = fmaxf(acc[mb][nb][2] + bb.x, 0.0f);
                float v3 = fmaxf(acc[mb][nb][3] + bb.y, 0.0f);
                uint32_t h0, l0w, h1w, l1w;
                asm("cvt.rn.bf16x2.f32 %0, %1, %2;" : "=r"(h0) : "f"(v1), "f"(v0));
                float r0 = v0 - __uint_as_float(h0 << 16);
                float r1 = v1 - __uint_as_float(h0 & 0xffff0000u);
                asm("cvt.rn.bf16x2.f32 %0, %1, %2;" : "=r"(l0w) : "f"(r1), "f"(r0));
                asm("cvt.rn.bf16x2.f32 %0, %1, %2;" : "=r"(h1w) : "f"(v3), "f"(v2));
                float r2 = v2 - __uint_as_float(h1w << 16);
                float r3 = v3 - __uint_as_float(h1w & 0xffff0000u);
                asm("cvt.rn.bf16x2.f32 %0, %1, %2;" : "=r"(l1w) : "f"(r3), "f"(r2));
                *(uint32_t*)(A2h + row * A2_STR + col * 2) = h0;
                *(uint32_t*)(A2l + row * A2_STR + col * 2) = l0w;
                *(uint32_t*)(A2h + (row + 8) * A2_STR + col * 2) = h1w;
                *(uint32_t*)(A2l + (row + 8) * A2_STR + col * 2) = l1w;
            }
        }
    }
    #pragma unroll
    for (int a = 0; a < 2; a++)
        #pragma unroll
        for (int b = 0; b < 8; b++)
            #pragma unroll
            for (int c = 0; c < 4; c++) acc[a][b][c] = 0.0f;
    __syncthreads();

    // ================= GEMM2: 4 chunks of 32 (single B2 buffer) =================
    #pragma unroll 1
    for (int c2 = 0; c2 < 4; c2++) {
        if (c2 > 0) {
            __syncthreads();                    // all reads of previous B2 chunk done
            b2fill(c2, smem + B2_OFF, tid);
            CP_COMMIT(); CP_WAIT0();
            __syncthreads();
        }
        const char* Ah = smem + A2H_OFF + c2 * 64;
        const char* Al = smem + A2L_OFF + c2 * 64;
        const char* Bh = smem + B2_OFF;
        const char* Bl = Bh + TILE1;
        uint32_t ah[2][4], al[2][4];
        #pragma unroll
        for (int s = 0; s < 8; s++)
            math_eighth(Ah, Al, Bh, Bl, s, wM, wN, g, tc, A2_STR, ah, al, acc);
    }

    // -------- epilogue 2: out = relu(D2 + b2) --------
    #pragma unroll
    for (int mb = 0; mb < 2; mb++) {
        int m1 = m0 + wM + mb * 16 + g;
        int m2 = m1 + 8;
        #pragma unroll
        for (int nb = 0; nb < 8; nb++) {
            int col = wN + nb * 8 + tc;
            float2 bb = *(const float2*)(b2 + col);
            if (m1 < NN) {
                float2 v = make_float2(fmaxf(acc[mb][nb][0] + bb.x, 0.0f),
                                       fmaxf(acc[mb][nb][1] + bb.y, 0.0f));
                *(float2*)(out + (size_t)m1 * HID + col) = v;
            }
            if (m2 < NN) {
                float2 v = make_float2(fmaxf(acc[mb][nb][2] + bb.x, 0.0f),
                                       fmaxf(acc[mb][nb][3] + bb.y, 0.0f));
                *(float2*)(out + (size_t)m2 * HID + col) = v;
            }
        }
    }
}

// ---------------- launch ----------------
extern "C" void kernel_launch(void* const* d_in, const int* in_sizes, int n_in,
                              void* d_out, int out_size)
{
    const float* verts = (const float*)d_in[0];
    const float* bb    = (const float*)d_in[1];
    const float* seg   = (const float*)d_in[2];
    const void*  edges = d_in[3];
    const float* W1    = (const float*)d_in[4];
    const float* b1    = (const float*)d_in[5];
    const float* W2    = (const float*)d_in[6];
    const float* b2    = (const float*)d_in[7];
    float* out = (float*)d_out;

    k_prep<<<PB_T, 256>>>((const int*)edges, W1, W2, bb, seg);
    k_degree<<<2048, 256>>>(edges);
    k_max<<<(NN + 255) / 256, 256>>>();

    cudaFuncSetAttribute(k_main, cudaFuncAttributeMaxDynamicSharedMemorySize, SMEM_BYTES);
    k_main<<<(NN + 127) / 128, 256, SMEM_BYTES>>>(verts, b1, b2, out);
}